// round 16
// baseline (speedup 1.0000x reference)
#include <cuda_runtime.h>
#include <cuda_bf16.h>
#include <stdint.h>

#define BUCKET_SIZE 512
#define G1    296               // pass1 blocks
#define WPB   8                 // warps per block
#define W     (G1 * WPB)        // 2368 warp-tiles
#define BG    8                 // block-groups for the block-level scan
#define RPB   (G1 / BG)         // 37 blocks per group
#define MAXNBP 8192             // padded bucket-row stride (actual nbp = 7816)
#define MAXN  4194304

// Scratch (static; no allocations)
__device__ unsigned char  g_pre8 [(size_t)W  * MAXNBP];          // 19.4MB within-block warp-exclusive prefix
__device__ unsigned       g_bsum [(size_t)G1 * MAXNBP];          //  9.25MB block sums -> block bases
__device__ unsigned       g_gp   [(size_t)BG * MAXNBP];          //  0.25MB group partials
__device__ unsigned       g_word [MAXN];                         // 16MB  b<<8 | warp-local rank
__device__ unsigned       g_cnt  [MAXNBP];                       // per-bucket totals
__device__ unsigned       g_inv  [(size_t)MAXNBP * BUCKET_SIZE]; // 16MB slot -> point idx

// ---- Pass 1: hash + warp-private u8 counting + shfl-free local rank ----
// Epilogue: within-block exclusive warp prefixes (u8) + per-block sums (u32).
__global__ __launch_bounds__(256) void psh_pass1(
    const float* __restrict__ coords, const int* __restrict__ seps,
    const int* __restrict__ hop_p, int n, int nB, int nb, int nbp, int wtile,
    unsigned long long magic_nb, float* __restrict__ out_bucket)
{
    extern __shared__ unsigned char cnt[];   // [WPB][nbp]
    const int lane = threadIdx.x & 31;
    const int wid  = threadIdx.x >> 5;
    const int nq   = nbp >> 2;
    for (int j = threadIdx.x; j < WPB * nq; j += 256)
        ((unsigned*)cnt)[j] = 0u;
    __syncthreads();
    unsigned char* cw = cnt + wid * nbp;

    const unsigned hop = (unsigned)hop_p[0];
    const int wt  = blockIdx.x * WPB + wid;
    const int beg = wt * wtile;
    const int end = min(n, beg + wtile);

    int klo = 0, khi = 0;
    if (beg < end) {
        for (int k = 0; k < nB; k++) {
            int s = __ldg(&seps[k]);
            klo += (s <= beg);
            khi += (s <= end - 1);
        }
    }

    int i = beg + lane;
    bool v = (i < end);
    float x = 0.f, y = 0.f, z = 0.f;
    if (v) { x = coords[3*i]; y = coords[3*i+1]; z = coords[3*i+2]; }

    for (int c = beg; c < end; c += 32) {
        int ni = i + 32;                       // prefetch next chunk
        bool vn = (ni < end);
        float nx = 0.f, ny = 0.f, nz = 0.f;
        if (vn) { nx = coords[3*ni]; ny = coords[3*ni+1]; nz = coords[3*ni+2]; }

        unsigned vm = __ballot_sync(0xffffffffu, v);
        if (v) {
            unsigned bid = (unsigned)klo;
            for (int k = klo; k < khi; k++) bid += (__ldg(&seps[k]) <= i);
            unsigned vx = (unsigned)(int)floorf(x);
            unsigned vy = (unsigned)(int)floorf(y);
            unsigned vz = (unsigned)(int)floorf(z);
            unsigned h = vx * 73856093u ^ vy * 19349663u ^ vz * 83492791u
                       ^ bid * 2654435761u;
            h += hop;
            unsigned q = (unsigned)__umul64hi((unsigned long long)h, magic_nb);
            unsigned b = h - q * (unsigned)nb;
            out_bucket[i] = (float)b;
            unsigned mask  = __match_any_sync(vm, b);
            unsigned intra = __popc(mask & ((1u << lane) - 1u));
            unsigned local = (unsigned)cw[b];          // group-broadcast read
            if (lane == (unsigned)(__ffs(mask) - 1))   // leader updates after reads
                cw[b] = (unsigned char)(local + __popc(mask));
            g_word[i] = (b << 8) | min(local + intra, 255u);
        }
        i = ni; v = vn; x = nx; y = ny; z = nz;
    }

    // epilogue: byte-SIMD exclusive warp prefix + block sums (each byte < 256)
    __syncthreads();
    const int wt0 = blockIdx.x * WPB;
    unsigned* bsum = g_bsum + (size_t)blockIdx.x * nbp;
    for (int q = threadIdx.x; q < nq; q += 256) {
        unsigned run = 0;
        #pragma unroll
        for (int w = 0; w < WPB; w++) {
            unsigned vv = ((const unsigned*)cnt)[w * nq + q];
            ((unsigned*)(g_pre8 + (size_t)(wt0 + w) * nbp))[q] = run;
            run += vv;
        }
        uint4 pk;
        pk.x = run & 255u;          pk.y = (run >> 8) & 255u;
        pk.z = (run >> 16) & 255u;  pk.w = run >> 24;
        *(uint4*)(bsum + q * 4) = pk;
    }
}

// ---- Scan A: per-group partial sums over 37 block rows (u32, coalesced) ----
__global__ __launch_bounds__(256) void psh_scanA(int nbp)
{
    int j = blockIdx.x * 256 + threadIdx.x;
    int g = blockIdx.y;
    if (j >= nbp) return;
    int r0 = g * RPB, r1 = r0 + RPB;
    unsigned s = 0;
    #pragma unroll 4
    for (int r = r0; r < r1; r++) s += g_bsum[(size_t)r * nbp + j];
    g_gp[(size_t)g * nbp + j] = s;
}

// ---- Scan B: chain-8 scan of group partials; emit counts ----
__global__ __launch_bounds__(256) void psh_scanB(
    int nb, int nbp, float* __restrict__ out_counts)
{
    int j = blockIdx.x * 256 + threadIdx.x;
    if (j >= nbp) return;
    unsigned carry = 0;
    #pragma unroll
    for (int g = 0; g < BG; g++) {
        size_t o = (size_t)g * nbp + j;
        unsigned v = g_gp[o];
        g_gp[o] = carry;
        carry += v;
    }
    if (j < nb) {
        g_cnt[j] = carry;
        out_counts[j] = (float)carry;
    }
}

// ---- Scan C: rescan 37 rows per group -> exclusive block bases in place ----
__global__ __launch_bounds__(256) void psh_scanC(int nbp)
{
    int j = blockIdx.x * 256 + threadIdx.x;
    int g = blockIdx.y;
    if (j >= nbp) return;
    int r0 = g * RPB, r1 = r0 + RPB;
    unsigned carry = g_gp[(size_t)g * nbp + j];
    #pragma unroll 4
    for (int r = r0; r < r1; r++) {
        size_t o = (size_t)r * nbp + j;
        unsigned v = g_bsum[o];
        g_bsum[o] = carry;
        carry += v;
    }
}

// ---- Scatter: smem-free streaming inv emission ----
__global__ __launch_bounds__(256) void psh_scatter(
    int n, int nbp, unsigned long long magic_w)
{
    int i = blockIdx.x * 256 + threadIdx.x;
    if (i >= n) return;
    unsigned wd = g_word[i];
    unsigned b  = wd >> 8;
    unsigned lr = wd & 255u;
    unsigned wt  = (unsigned)__umul64hi((unsigned long long)i, magic_w);
    unsigned blk = wt >> 3;   // WPB = 8
    unsigned rank = __ldg(&g_bsum[(size_t)blk * nbp + b])
                  + (unsigned)__ldg(&g_pre8[(size_t)wt * nbp + b]) + lr;
    if (rank < BUCKET_SIZE)
        g_inv[(size_t)b * BUCKET_SIZE + rank] = (unsigned)i;
}

// ---- Pass 4: gather — coalesced full-sector output writes (proven shape) ----
__global__ __launch_bounds__(256) void psh_pass4(
    const float* __restrict__ coords, int pad_to,
    float* __restrict__ out_coord)
{
    int s = blockIdx.x * 256 + threadIdx.x;
    if (s >= pad_to) return;
    int b = s >> 9;
    int r = s & (BUCKET_SIZE - 1);
    float x = 0.f, y = 0.f, z = 0.f;
    if ((unsigned)r < g_cnt[b]) {
        unsigned i = g_inv[s];
        x = __ldg(&coords[3*i]);
        y = __ldg(&coords[3*i+1]);
        z = __ldg(&coords[3*i+2]);
    }
    out_coord[(size_t)s * 3 + 0] = x;
    out_coord[(size_t)s * 3 + 1] = y;
    out_coord[(size_t)s * 3 + 2] = z;
}

extern "C" void kernel_launch(void* const* d_in, const int* in_sizes, int n_in,
                              void* d_out, int out_size)
{
    const float* coords = (const float*)d_in[0];
    const int*   seps   = (const int*)d_in[1];
    const int*   hop_p  = (const int*)d_in[2];

    const int n  = in_sizes[0] / 3;
    const int nB = in_sizes[1];
    const int pad_to = ((n + BUCKET_SIZE - 1) / BUCKET_SIZE) * BUCKET_SIZE;
    const int nb  = pad_to / BUCKET_SIZE;
    const int nbp = (nb + 7) & ~7;           // padded row stride (mult of 8)
    const int wtile = (n + W - 1) / W;       // 1690 for n=4M

    float* out_coord  = (float*)d_out;
    float* out_counts = out_coord + (size_t)pad_to * 3;
    float* out_bucket = out_counts + nb;

    unsigned long long magic_nb = (~0ULL) / (unsigned)nb + 1ULL;     // h % nb
    unsigned long long magic_w  = (~0ULL) / (unsigned)wtile + 1ULL;  // i / wtile

    size_t shw = (size_t)WPB * nbp;          // ~62.5 KB -> 3 blocks/SM

    static bool attr_set = false;
    if (!attr_set) {
        cudaFuncSetAttribute(psh_pass1,
                             cudaFuncAttributeMaxDynamicSharedMemorySize,
                             WPB * MAXNBP);
        attr_set = true;
    }

    dim3 gscan((nbp + 255) / 256, BG);
    psh_pass1<<<G1, 256, shw>>>(coords, seps, hop_p, n, nB, nb, nbp, wtile,
                                magic_nb, out_bucket);
    psh_scanA<<<gscan, 256>>>(nbp);
    psh_scanB<<<(nbp + 255) / 256, 256>>>(nb, nbp, out_counts);
    psh_scanC<<<gscan, 256>>>(nbp);
    psh_scatter<<<(n + 255) / 256, 256>>>(n, nbp, magic_w);
    psh_pass4<<<(pad_to + 255) / 256, 256>>>(coords, pad_to, out_coord);
}

// round 17
// speedup vs baseline: 1.4808x; 1.4808x over previous
#include <cuda_runtime.h>
#include <cuda_bf16.h>
#include <stdint.h>

#define BUCKET_SIZE 512
#define G1    296               // pass1 blocks
#define WPB   8                 // warps per block
#define W     (G1 * WPB)        // 2368 warp-tiles
#define BG    8                 // block-groups for the block-level scan
#define RPB   (G1 / BG)         // 37 blocks per group
#define MAXNBP 8192             // padded bucket-row stride (actual nbp = 7816)
#define MAXN  4194304

// Scratch (static; no allocations)
__device__ unsigned char  g_pre8 [(size_t)W  * MAXNBP];          // 19.4MB within-block warp-exclusive prefix
__device__ unsigned       g_bsum [(size_t)G1 * MAXNBP];          //  9.25MB per-block sums
__device__ unsigned       g_bbase[(size_t)G1 * MAXNBP];          //  9.25MB exclusive block bases (no aliasing!)
__device__ unsigned       g_gp   [(size_t)BG * MAXNBP];          //  0.25MB group partials
__device__ unsigned       g_gpe  [(size_t)BG * MAXNBP];          //  0.25MB group exclusive bases
__device__ unsigned       g_word [MAXN];                         // 16MB  b<<8 | warp-local rank
__device__ unsigned       g_cnt  [MAXNBP];                       // per-bucket totals
__device__ unsigned       g_inv  [(size_t)MAXNBP * BUCKET_SIZE]; // 16MB slot -> point idx

// ---- Pass 1: hash + warp-private u8 counting + shfl-free local rank ----
// Epilogue: within-block exclusive warp prefixes (u8) + per-block sums (u32).
__global__ __launch_bounds__(256) void psh_pass1(
    const float* __restrict__ coords, const int* __restrict__ seps,
    const int* __restrict__ hop_p, int n, int nB, int nb, int nbp, int wtile,
    unsigned long long magic_nb, float* __restrict__ out_bucket)
{
    extern __shared__ unsigned char cnt[];   // [WPB][nbp]
    const int lane = threadIdx.x & 31;
    const int wid  = threadIdx.x >> 5;
    const int nq   = nbp >> 2;
    for (int j = threadIdx.x; j < WPB * nq; j += 256)
        ((unsigned*)cnt)[j] = 0u;
    __syncthreads();
    unsigned char* cw = cnt + wid * nbp;

    const unsigned hop = (unsigned)hop_p[0];
    const int wt  = blockIdx.x * WPB + wid;
    const int beg = wt * wtile;
    const int end = min(n, beg + wtile);

    int klo = 0, khi = 0;
    if (beg < end) {
        for (int k = 0; k < nB; k++) {
            int s = __ldg(&seps[k]);
            klo += (s <= beg);
            khi += (s <= end - 1);
        }
    }

    int i = beg + lane;
    bool v = (i < end);
    float x = 0.f, y = 0.f, z = 0.f;
    if (v) { x = coords[3*i]; y = coords[3*i+1]; z = coords[3*i+2]; }

    for (int c = beg; c < end; c += 32) {
        int ni = i + 32;                       // prefetch next chunk
        bool vn = (ni < end);
        float nx = 0.f, ny = 0.f, nz = 0.f;
        if (vn) { nx = coords[3*ni]; ny = coords[3*ni+1]; nz = coords[3*ni+2]; }

        unsigned vm = __ballot_sync(0xffffffffu, v);
        if (v) {
            unsigned bid = (unsigned)klo;
            for (int k = klo; k < khi; k++) bid += (__ldg(&seps[k]) <= i);
            unsigned vx = (unsigned)(int)floorf(x);
            unsigned vy = (unsigned)(int)floorf(y);
            unsigned vz = (unsigned)(int)floorf(z);
            unsigned h = vx * 73856093u ^ vy * 19349663u ^ vz * 83492791u
                       ^ bid * 2654435761u;
            h += hop;
            unsigned q = (unsigned)__umul64hi((unsigned long long)h, magic_nb);
            unsigned b = h - q * (unsigned)nb;
            out_bucket[i] = (float)b;
            unsigned mask  = __match_any_sync(vm, b);
            unsigned intra = __popc(mask & ((1u << lane) - 1u));
            unsigned local = (unsigned)cw[b];          // group-broadcast read
            if (lane == (unsigned)(__ffs(mask) - 1))   // leader updates after reads
                cw[b] = (unsigned char)(local + __popc(mask));
            g_word[i] = (b << 8) | min(local + intra, 255u);
        }
        i = ni; v = vn; x = nx; y = ny; z = nz;
    }

    // epilogue: byte-SIMD exclusive warp prefix + block sums (each byte < 256)
    __syncthreads();
    const int wt0 = blockIdx.x * WPB;
    unsigned* bsum = g_bsum + (size_t)blockIdx.x * nbp;
    for (int q = threadIdx.x; q < nq; q += 256) {
        unsigned run = 0;
        #pragma unroll
        for (int w = 0; w < WPB; w++) {
            unsigned vv = ((const unsigned*)cnt)[w * nq + q];
            ((unsigned*)(g_pre8 + (size_t)(wt0 + w) * nbp))[q] = run;
            run += vv;
        }
        uint4 pk;
        pk.x = run & 255u;          pk.y = (run >> 8) & 255u;
        pk.z = (run >> 16) & 255u;  pk.w = run >> 24;
        *(uint4*)(bsum + q * 4) = pk;
    }
}

// ---- Scan A: per-group partial sums over 37 block rows (u32, coalesced) ----
__global__ __launch_bounds__(256) void psh_scanA(int nbp)
{
    int j = blockIdx.x * 256 + threadIdx.x;
    int g = blockIdx.y;
    if (j >= nbp) return;
    int r0 = g * RPB, r1 = r0 + RPB;
    unsigned s = 0;
    #pragma unroll 4
    for (int r = r0; r < r1; r++) s += g_bsum[(size_t)r * nbp + j];
    g_gp[(size_t)g * nbp + j] = s;
}

// ---- Scan B: chain-8 scan of group partials -> g_gpe (separate array); counts ----
__global__ __launch_bounds__(256) void psh_scanB(
    int nb, int nbp, float* __restrict__ out_counts)
{
    int j = blockIdx.x * 256 + threadIdx.x;
    if (j >= nbp) return;
    unsigned carry = 0;
    #pragma unroll
    for (int g = 0; g < BG; g++) {
        size_t o = (size_t)g * nbp + j;
        unsigned v = g_gp[o];       // read-only array
        g_gpe[o] = carry;           // write to distinct array: loads batch freely
        carry += v;
    }
    if (j < nb) {
        g_cnt[j] = carry;
        out_counts[j] = (float)carry;
    }
}

// ---- Scan C: rescan 37 rows per group -> g_bbase (separate array, no aliasing) ----
__global__ __launch_bounds__(256) void psh_scanC(int nbp)
{
    int j = blockIdx.x * 256 + threadIdx.x;
    int g = blockIdx.y;
    if (j >= nbp) return;
    int r0 = g * RPB, r1 = r0 + RPB;
    unsigned carry = g_gpe[(size_t)g * nbp + j];
    #pragma unroll 4
    for (int r = r0; r < r1; r++) {
        size_t o = (size_t)r * nbp + j;
        unsigned v = g_bsum[o];     // read-only array
        g_bbase[o] = carry;         // write to distinct array: loads batch freely
        carry += v;
    }
}

// ---- Scatter: smem-free streaming inv emission ----
__global__ __launch_bounds__(256) void psh_scatter(
    int n, int nbp, unsigned long long magic_w)
{
    int i = blockIdx.x * 256 + threadIdx.x;
    if (i >= n) return;
    unsigned wd = g_word[i];
    unsigned b  = wd >> 8;
    unsigned lr = wd & 255u;
    unsigned wt  = (unsigned)__umul64hi((unsigned long long)i, magic_w);
    unsigned blk = wt >> 3;   // WPB = 8
    unsigned rank = __ldg(&g_bbase[(size_t)blk * nbp + b])
                  + (unsigned)__ldg(&g_pre8[(size_t)wt * nbp + b]) + lr;
    if (rank < BUCKET_SIZE)
        g_inv[(size_t)b * BUCKET_SIZE + rank] = (unsigned)i;
}

// ---- Pass 4: gather — coalesced full-sector output writes (proven shape) ----
__global__ __launch_bounds__(256) void psh_pass4(
    const float* __restrict__ coords, int pad_to,
    float* __restrict__ out_coord)
{
    int s = blockIdx.x * 256 + threadIdx.x;
    if (s >= pad_to) return;
    int b = s >> 9;
    int r = s & (BUCKET_SIZE - 1);
    float x = 0.f, y = 0.f, z = 0.f;
    if ((unsigned)r < g_cnt[b]) {
        unsigned i = g_inv[s];
        x = __ldg(&coords[3*i]);
        y = __ldg(&coords[3*i+1]);
        z = __ldg(&coords[3*i+2]);
    }
    out_coord[(size_t)s * 3 + 0] = x;
    out_coord[(size_t)s * 3 + 1] = y;
    out_coord[(size_t)s * 3 + 2] = z;
}

extern "C" void kernel_launch(void* const* d_in, const int* in_sizes, int n_in,
                              void* d_out, int out_size)
{
    const float* coords = (const float*)d_in[0];
    const int*   seps   = (const int*)d_in[1];
    const int*   hop_p  = (const int*)d_in[2];

    const int n  = in_sizes[0] / 3;
    const int nB = in_sizes[1];
    const int pad_to = ((n + BUCKET_SIZE - 1) / BUCKET_SIZE) * BUCKET_SIZE;
    const int nb  = pad_to / BUCKET_SIZE;
    const int nbp = (nb + 7) & ~7;           // padded row stride (mult of 8)
    const int wtile = (n + W - 1) / W;       // 1690 for n=4M

    float* out_coord  = (float*)d_out;
    float* out_counts = out_coord + (size_t)pad_to * 3;
    float* out_bucket = out_counts + nb;

    unsigned long long magic_nb = (~0ULL) / (unsigned)nb + 1ULL;     // h % nb
    unsigned long long magic_w  = (~0ULL) / (unsigned)wtile + 1ULL;  // i / wtile

    size_t shw = (size_t)WPB * nbp;          // ~62.5 KB -> 3 blocks/SM

    static bool attr_set = false;
    if (!attr_set) {
        cudaFuncSetAttribute(psh_pass1,
                             cudaFuncAttributeMaxDynamicSharedMemorySize,
                             WPB * MAXNBP);
        attr_set = true;
    }

    dim3 gscan((nbp + 255) / 256, BG);
    psh_pass1<<<G1, 256, shw>>>(coords, seps, hop_p, n, nB, nb, nbp, wtile,
                                magic_nb, out_bucket);
    psh_scanA<<<gscan, 256>>>(nbp);
    psh_scanB<<<(nbp + 255) / 256, 256>>>(nb, nbp, out_counts);
    psh_scanC<<<gscan, 256>>>(nbp);
    psh_scatter<<<(n + 255) / 256, 256>>>(n, nbp, magic_w);
    psh_pass4<<<(pad_to + 255) / 256, 256>>>(coords, pad_to, out_coord);
}